// round 17
// baseline (speedup 1.0000x reference)
#include <cuda_runtime.h>
#include <cuda_bf16.h>
#include <math.h>

#define N_   8192
#define D_   2048
#define P_   512
#define NB_  16          // k0 partition blocks (512 samples each)
#define EPSF 1e-12f
#define S_   4           // k1 LDGSTS ring depth (4 x 8KB static smem)

// ---------------- scratch (device globals; no allocation allowed) ----------
__device__ int   g_count[P_];
__device__ int   g_offset[P_];
__device__ int   g_members[N_];
__device__ __nv_bfloat16 g_cbf[3][P_][D_];   // unit centers, bf16
__device__ float g_part[3][4][P_][P_];       // split-K partial dot planes (12MB)
__device__ float g_sumnorm;                  // sum ||s_c|| over all (m, c)
__device__ float g_rlsum;                    // sum of row losses
__device__ unsigned g_done;                  // k3 completion counter

// ---------------- helpers --------------------------------------------------
__device__ __forceinline__ float warpSum(float v) {
#pragma unroll
    for (int o = 16; o; o >>= 1) v += __shfl_xor_sync(0xffffffffu, v, o);
    return v;
}
__device__ __forceinline__ unsigned bfpack(float lo, float hi) {
    unsigned a = (unsigned)__bfloat16_as_ushort(__float2bfloat16_rn(lo));
    unsigned b = (unsigned)__bfloat16_as_ushort(__float2bfloat16_rn(hi));
    return a | (b << 16);
}
__device__ __forceinline__ float dot8(const float4& x, const float4& y) {
    return x.x * x.x + x.y * x.y + x.z * x.z + x.w * x.w
         + y.x * y.x + y.y * y.y + y.z * y.z + y.w * y.w;
}
__device__ __forceinline__ void cpa16(void* dst, const void* src) {
    unsigned d = (unsigned)__cvta_generic_to_shared(dst);
    asm volatile("cp.async.cg.shared.global [%0], [%1], 16;\n" :: "r"(d), "l"(src));
}
__device__ __forceinline__ void cpa_commit() {
    asm volatile("cp.async.commit_group;\n" ::: "memory");
}
template <int Npend>
__device__ __forceinline__ void cpa_wait() {
    asm volatile("cp.async.wait_group %0;\n" :: "n"(Npend) : "memory");
}

// ---------------- kernel 0: member list build, ONE launch (grid NB_) -------
__global__ void __launch_bounds__(512) k0_all(const int* __restrict__ label) {
    __shared__ int tot[P_], bef[P_];
    __shared__ int ws[16];
    int t = threadIdx.x, b = blockIdx.x, lane = t & 31, w = t >> 5;

    tot[t] = 0; bef[t] = 0;
    __syncthreads();
    int myl = 0;
#pragma unroll
    for (int j = 0; j < NB_; j++) {
        int l = __ldg(&label[j * 512 + t]);
        if (j == b) myl = l;
        atomicAdd(&tot[l], 1);
        if (j < b) atomicAdd(&bef[l], 1);
    }
    __syncthreads();

    int mytot = tot[t];
    int inc = mytot;
#pragma unroll
    for (int o = 1; o < 32; o <<= 1) {
        int v = __shfl_up_sync(0xffffffffu, inc, o);
        if (lane >= o) inc += v;
    }
    if (lane == 31) ws[w] = inc;
    __syncthreads();
    if (t < 32) {
        int v = (t < 16) ? ws[t] : 0;
        int s = v;
#pragma unroll
        for (int o = 1; o < 32; o <<= 1) {
            int u = __shfl_up_sync(0xffffffffu, s, o);
            if (lane >= o) s += u;
        }
        if (t < 16) ws[t] = s - v;
    }
    __syncthreads();
    int exc = ws[w] + inc - mytot;        // exclusive class prefix
    if (b == 0) {
        g_count[t]  = mytot;
        g_offset[t] = exc;
        if (t == 0) { g_sumnorm = 0.f; g_rlsum = 0.f; g_done = 0u; }
    }
    bef[t] = exc + bef[t];                // this partition's write cursor
    __syncthreads();
    int pos = atomicAdd(&bef[myl], 1);
    g_members[pos] = b * 512 + t;
}

// ---------------- kernel 1: centers, LDGSTS ring + row pairing -------------
// grid (P_, 3), block 256. 4-stage ring; two rows per barrier.
__global__ void __launch_bounds__(256) k1_centers(const float* __restrict__ f0,
                                                  const float* __restrict__ f1,
                                                  const float* __restrict__ f2) {
    int c = blockIdx.x, m = blockIdx.y;
    const float* f = (m == 0) ? f0 : ((m == 1) ? f1 : f2);
    int off = g_offset[c];
    int K   = g_count[c];
    int t   = threadIdx.x, w = t >> 5, lane = t & 31;

    __shared__ __align__(16) float stg[S_][D_];   // 32 KB ring
    __shared__ float wred[2][2][8];               // [pair parity][row][warp]

#pragma unroll
    for (int s = 0; s < S_; s++) {
        if (s < K) {
            int row = __ldg(&g_members[off + s]);
            const float* src = f + (size_t)row * D_;
            cpa16(&stg[s][t * 4], src + t * 4);
            cpa16(&stg[s][1024 + t * 4], src + 1024 + t * 4);
        }
        cpa_commit();
    }

    float a0 = 0.f, a1 = 0.f, a2 = 0.f, a3 = 0.f;
    float a4 = 0.f, a5 = 0.f, a6 = 0.f, a7 = 0.f;

    int k = 0;
    for (; k + 1 < K; k += 2) {
        cpa_wait<S_ - 2>();          // stages k and k+1 landed
        int sb0 = k & (S_ - 1), sb1 = (k + 1) & (S_ - 1);
        float4 x0 = *(const float4*)&stg[sb0][t * 4];
        float4 y0 = *(const float4*)&stg[sb0][1024 + t * 4];
        float4 x1 = *(const float4*)&stg[sb1][t * 4];
        float4 y1 = *(const float4*)&stg[sb1][1024 + t * 4];
        int kn0 = k + S_, kn1 = k + 1 + S_;
        if (kn0 < K) {
            int row = __ldg(&g_members[off + kn0]);
            const float* src = f + (size_t)row * D_;
            cpa16(&stg[sb0][t * 4], src + t * 4);
            cpa16(&stg[sb0][1024 + t * 4], src + 1024 + t * 4);
        }
        cpa_commit();
        if (kn1 < K) {
            int row = __ldg(&g_members[off + kn1]);
            const float* src = f + (size_t)row * D_;
            cpa16(&stg[sb1][t * 4], src + t * 4);
            cpa16(&stg[sb1][1024 + t * 4], src + 1024 + t * 4);
        }
        cpa_commit();

        float ss0 = dot8(x0, y0), ss1 = dot8(x1, y1);
#pragma unroll
        for (int o = 16; o; o >>= 1) {     // two interleaved shfl chains (ILP)
            ss0 += __shfl_xor_sync(0xffffffffu, ss0, o);
            ss1 += __shfl_xor_sync(0xffffffffu, ss1, o);
        }
        int pb = (k >> 1) & 1;
        if (lane == 0) { wred[pb][0][w] = ss0; wred[pb][1][w] = ss1; }
        __syncthreads();                   // ONE barrier per two rows
        float t0 = wred[pb][0][0] + wred[pb][0][1] + wred[pb][0][2] + wred[pb][0][3]
                 + wred[pb][0][4] + wred[pb][0][5] + wred[pb][0][6] + wred[pb][0][7];
        float t1 = wred[pb][1][0] + wred[pb][1][1] + wred[pb][1][2] + wred[pb][1][3]
                 + wred[pb][1][4] + wred[pb][1][5] + wred[pb][1][6] + wred[pb][1][7];
        float i0 = rsqrtf(fmaxf(t0, 1e-24f));
        float i1 = rsqrtf(fmaxf(t1, 1e-24f));
        a0 += x0.x * i0 + x1.x * i1; a1 += x0.y * i0 + x1.y * i1;
        a2 += x0.z * i0 + x1.z * i1; a3 += x0.w * i0 + x1.w * i1;
        a4 += y0.x * i0 + y1.x * i1; a5 += y0.y * i0 + y1.y * i1;
        a6 += y0.z * i0 + y1.z * i1; a7 += y0.w * i0 + y1.w * i1;
    }
    if (k < K) {                     // odd tail row
        cpa_wait<0>();
        int sb = k & (S_ - 1);
        float4 x = *(const float4*)&stg[sb][t * 4];
        float4 y = *(const float4*)&stg[sb][1024 + t * 4];
        float ss = warpSum(dot8(x, y));
        if (lane == 0) wred[0][0][w] = ss;
        __syncthreads();
        float tt = wred[0][0][0] + wred[0][0][1] + wred[0][0][2] + wred[0][0][3]
                 + wred[0][0][4] + wred[0][0][5] + wred[0][0][6] + wred[0][0][7];
        float iv = rsqrtf(fmaxf(tt, 1e-24f));
        a0 += x.x * iv; a1 += x.y * iv; a2 += x.z * iv; a3 += x.w * iv;
        a4 += y.x * iv; a5 += y.y * iv; a6 += y.z * iv; a7 += y.w * iv;
    }

    float ss2 = a0 * a0 + a1 * a1 + a2 * a2 + a3 * a3
              + a4 * a4 + a5 * a5 + a6 * a6 + a7 * a7;
    ss2 = warpSum(ss2);
    __syncthreads();
    if (lane == 0) wred[0][0][w] = ss2;
    __syncthreads();
    float tot2 = wred[0][0][0] + wred[0][0][1] + wred[0][0][2] + wred[0][0][3]
               + wred[0][0][4] + wred[0][0][5] + wred[0][0][6] + wred[0][0][7];
    float nrm  = sqrtf(tot2);
    float inv2 = 1.f / fmaxf(nrm, EPSF);

    __nv_bfloat16* cb = &g_cbf[m][c][0];
    uint2 u0, u1;
    u0.x = bfpack(a0 * inv2, a1 * inv2); u0.y = bfpack(a2 * inv2, a3 * inv2);
    u1.x = bfpack(a4 * inv2, a5 * inv2); u1.y = bfpack(a6 * inv2, a7 * inv2);
    *(uint2*)(cb + 4 * t)         = u0;
    *(uint2*)(cb + 4 * (t + 256)) = u1;
    if (t == 0) atomicAdd(&g_sumnorm, nrm);
}

// ---------------- kernel 2: split-K bf16 mma GEMM, 3-stage cp.async --------
// grid (8, 8, 12): z = p*4 + ks. 64x64 tile over K=512 (8 chunks of 64).
#define KC_ 64
#define NC_ (512 / KC_)
__device__ __forceinline__ unsigned sw_off(int row, int g) {
    return (unsigned)(row * 128 + ((g ^ (row & 7)) << 4));
}

__global__ void __launch_bounds__(128) k2_gemm() {
    __shared__ __align__(16) unsigned char As[3][64 * 128];
    __shared__ __align__(16) unsigned char Bs[3][64 * 128];

    int z  = blockIdx.z;
    int p  = z >> 2, ks = z & 3;
    int pa = (p == 2) ? 1 : 0;
    int pb = (p == 0) ? 1 : 2;
    const __nv_bfloat16* A = &g_cbf[pa][0][0];
    const __nv_bfloat16* B = &g_cbf[pb][0][0];

    int t = threadIdx.x, lane = t & 31, warp = t >> 5;
    int wr = warp >> 1, wc = warp & 1;
    int brow = blockIdx.y * 64, bcol = blockIdx.x * 64;
    int k0 = ks * 512;

    float acc[2][4][4];
#pragma unroll
    for (int mt = 0; mt < 2; mt++)
#pragma unroll
        for (int nt = 0; nt < 4; nt++)
#pragma unroll
            for (int e = 0; e < 4; e++) acc[mt][nt][e] = 0.f;

    int rsel = lane & 15, gsel = lane >> 4;

    // prologue: chunks 0 and 1 into stages 0 and 1
#pragma unroll
    for (int s = 0; s < 2; s++) {
        int co = k0 + s * KC_;
#pragma unroll
        for (int j = 0; j < 4; j++) {
            int i = t + j * 128, row = i >> 3, g = i & 7;
            cpa16(&As[s][sw_off(row, g)], A + (size_t)(brow + row) * D_ + co + g * 8);
            cpa16(&Bs[s][sw_off(row, g)], B + (size_t)(bcol + row) * D_ + co + g * 8);
        }
        cpa_commit();
    }

    for (int lc = 0; lc < NC_; lc++) {
        cpa_wait<1>();             // chunk lc landed (lc+1 may still fly)
        __syncthreads();           // prev iter's reads of stage (lc+2)%3 done

        if (lc + 2 < NC_) {        // refill the just-freed stage
            int ns = (lc + 2) % 3;
            int co = k0 + (lc + 2) * KC_;
#pragma unroll
            for (int j = 0; j < 4; j++) {
                int i = t + j * 128, row = i >> 3, g = i & 7;
                cpa16(&As[ns][sw_off(row, g)], A + (size_t)(brow + row) * D_ + co + g * 8);
                cpa16(&Bs[ns][sw_off(row, g)], B + (size_t)(bcol + row) * D_ + co + g * 8);
            }
        }
        cpa_commit();              // real or empty: keeps wait<1> exact

        int st = lc % 3;
        unsigned ab = (unsigned)__cvta_generic_to_shared(&As[st][0]);
        unsigned bb = (unsigned)__cvta_generic_to_shared(&Bs[st][0]);
#pragma unroll
        for (int kh = 0; kh < 4; kh++) {
            unsigned af[2][4], bfr[2][4];
#pragma unroll
            for (int mt = 0; mt < 2; mt++) {
                unsigned ad = ab + sw_off(wr * 32 + mt * 16 + rsel, kh * 2 + gsel);
                asm volatile("ldmatrix.sync.aligned.m8n8.x4.shared.b16 {%0,%1,%2,%3}, [%4];"
                             : "=r"(af[mt][0]), "=r"(af[mt][1]), "=r"(af[mt][2]), "=r"(af[mt][3])
                             : "r"(ad));
            }
#pragma unroll
            for (int np = 0; np < 2; np++) {
                unsigned bd = bb + sw_off(wc * 32 + np * 16 + rsel, kh * 2 + gsel);
                asm volatile("ldmatrix.sync.aligned.m8n8.x4.shared.b16 {%0,%1,%2,%3}, [%4];"
                             : "=r"(bfr[np][0]), "=r"(bfr[np][1]), "=r"(bfr[np][2]), "=r"(bfr[np][3])
                             : "r"(bd));
            }
#pragma unroll
            for (int mt = 0; mt < 2; mt++)
#pragma unroll
                for (int nt = 0; nt < 4; nt++) {
                    int np = nt >> 1, s = nt & 1;
                    asm volatile(
                        "mma.sync.aligned.m16n8k16.row.col.f32.bf16.bf16.f32 "
                        "{%0,%1,%2,%3},{%4,%5,%6,%7},{%8,%9},{%0,%1,%2,%3};"
                        : "+f"(acc[mt][nt][0]), "+f"(acc[mt][nt][1]),
                          "+f"(acc[mt][nt][2]), "+f"(acc[mt][nt][3])
                        : "r"(af[mt][0]), "r"(af[mt][1]), "r"(af[mt][2]), "r"(af[mt][3]),
                          "r"(bfr[np][0 + s]), "r"(bfr[np][2 + s]));
                }
        }
    }

    float* C = &g_part[p][ks][0][0];
#pragma unroll
    for (int mt = 0; mt < 2; mt++)
#pragma unroll
        for (int nt = 0; nt < 4; nt++) {
            int row = brow + wr * 32 + mt * 16 + (lane >> 2);
            int col = bcol + wc * 32 + nt * 8 + (lane & 3) * 2;
            *(float2*)(C + (size_t)row * P_ + col)       = make_float2(acc[mt][nt][0], acc[mt][nt][1]);
            *(float2*)(C + (size_t)(row + 8) * P_ + col) = make_float2(acc[mt][nt][2], acc[mt][nt][3]);
        }
}

// ---------------- kernel 3: combine splits + exp-sum + diag + FINAL --------
// grid 768, block 256: 8 warps = 2 rows x 4 warps. Each warp owns a 128-col
// quarter of one row (4 plane-loads/lane, MLP-4). ~6144 warps chip-wide.
__global__ void __launch_bounds__(256) k3_row(float* __restrict__ out) {
    int warp = threadIdx.x >> 5, lane = threadIdx.x & 31;
    int rib = warp >> 2;                      // row-in-block: 0..1
    int q   = warp & 3;                       // column quarter: 0..3
    int gid = blockIdx.x * 2 + rib;           // 0 .. 1535
    int p = gid >> 9, i = gid & (P_ - 1);
    const float* b0 = &g_part[p][0][i][0];    // plane stride P_*P_

    int c0 = q * 128 + lane * 4;
    float4 v0 = *(const float4*)(b0 + c0);
    float4 v1 = *(const float4*)(b0 + P_ * P_ + c0);
    float4 v2 = *(const float4*)(b0 + 2 * P_ * P_ + c0);
    float4 v3 = *(const float4*)(b0 + 3 * P_ * P_ + c0);
    float sx = v0.x + v1.x + v2.x + v3.x;
    float sy = v0.y + v1.y + v2.y + v3.y;
    float sz = v0.z + v1.z + v2.z + v3.z;
    float sw = v0.w + v1.w + v2.w + v3.w;

    float es = __expf(2.f * sx) + __expf(2.f * sy)
             + __expf(2.f * sz) + __expf(2.f * sw);
    float dg = 0.f;
    if (i == c0)     dg = sx;
    else if (i == c0 + 1) dg = sy;
    else if (i == c0 + 2) dg = sz;
    else if (i == c0 + 3) dg = sw;

    es = warpSum(es);
    dg = warpSum(dg);

    __shared__ float wes[2][4], wdg[2][4];
    if (lane == 0) { wes[rib][q] = es; wdg[rib][q] = dg; }
    __syncthreads();
    if (threadIdx.x == 0) {
        float r0 = __logf(wes[0][0] + wes[0][1] + wes[0][2] + wes[0][3])
                 - 2.f * (wdg[0][0] + wdg[0][1] + wdg[0][2] + wdg[0][3]);
        float r1 = __logf(wes[1][0] + wes[1][1] + wes[1][2] + wes[1][3])
                 - 2.f * (wdg[1][0] + wdg[1][1] + wdg[1][2] + wdg[1][3]);
        atomicAdd(&g_rlsum, r0 + r1);
        __threadfence();
        unsigned old = atomicAdd(&g_done, 1u);
        if (old == 767u) {                    // last block assembles the loss
            __threadfence();
            float R = atomicAdd(&g_rlsum, 0.f);
            out[0] = 6.f - g_sumnorm / 4096.f + R / 512.f;
        }
    }
}

// ---------------- launch: serial single stream -----------------------------
extern "C" void kernel_launch(void* const* d_in, const int* in_sizes, int n_in,
                              void* d_out, int out_size) {
    const float* fv    = (const float*)d_in[0];
    const float* fa    = (const float*)d_in[1];
    const float* fr    = (const float*)d_in[2];
    const int*   label = (const int*)d_in[3];
    (void)in_sizes; (void)n_in; (void)out_size;

    k0_all<<<NB_, 512>>>(label);
    k1_centers<<<dim3(P_, 3), 256>>>(fv, fa, fr);
    k2_gemm<<<dim3(8, 8, 12), 128>>>();
    k3_row<<<768, 256>>>((float*)d_out);
}